// round 1
// baseline (speedup 1.0000x reference)
#include <cuda_runtime.h>
#include <cuda_bf16.h>

// DensityEstimator: per-channel 1->3->3->3->1 MLP, p = cdf(x+.5) - cdf(x-.5)
// 192 channels, 65536 batch. softplus(H)/tanh(a) are batch-invariant: computed
// once per thread into registers. Grid-stride is a multiple of 192 so each
// thread's channel is fixed for its whole lifetime.

#define NCH 192
#define NBLK 888          // 888*256 = 227328 = 192*1184 -> channel invariant
#define NTHR 256

__device__ __forceinline__ float ex2a(float x) {
    float r; asm("ex2.approx.ftz.f32 %0, %1;" : "=f"(r) : "f"(x)); return r;
}
__device__ __forceinline__ float rcpa(float x) {
    float r; asm("rcp.approx.ftz.f32 %0, %1;" : "=f"(r) : "f"(x)); return r;
}

// Branch-free accurate-enough tanh: t = 1 - 2/(1+exp(2|v|)), sign-injected.
// abs err ~3e-7 (ex2/rcp approx are ~2^-22 rel). 2 MUFU + 4 ALU/FMA.
__device__ __forceinline__ float fast_tanh(float v) {
    float av = fabsf(v);
    float e  = ex2a(av * 2.8853900817779268f);   // exp(2*av)
    float r  = rcpa(e + 1.0f);
    float t  = fmaf(-2.0f, r, 1.0f);             // in [0,1]
    return __int_as_float(__float_as_int(t) | (__float_as_int(v) & 0x80000000));
}

__device__ __forceinline__ float fast_sigmoid(float v) {
    float e = ex2a(-1.4426950408889634f * v);    // exp(-v)
    return rcpa(1.0f + e);
}

// Accurate softplus for the one-time weight transform.
__device__ __forceinline__ float softplus_acc(float h) {
    return (h > 15.0f) ? h : log1pf(expf(h));
}

__global__ void __launch_bounds__(NTHR) de_kernel(
    const float* __restrict__ x,
    const float* __restrict__ a0, const float* __restrict__ a1, const float* __restrict__ a2,
    const float* __restrict__ b0, const float* __restrict__ b1, const float* __restrict__ b2,
    const float* __restrict__ b3,
    const float* __restrict__ H0, const float* __restrict__ H1, const float* __restrict__ H2,
    const float* __restrict__ H3,
    float* __restrict__ out, int n)
{
    const int stride = gridDim.x * blockDim.x;      // multiple of 192
    const int i0 = blockIdx.x * blockDim.x + threadIdx.x;
    const int c  = i0 % NCH;                        // fixed channel for this thread

    // One-time per-thread weight transform into registers (43 floats).
    float sh0[3], sh1[9], sh2[9], sh3[3];
    float ta0[3], ta1[3], ta2[3];
    float bb0[3], bb1[3], bb2[3], bb3;
#pragma unroll
    for (int j = 0; j < 3; j++) {
        sh0[j] = softplus_acc(__ldg(&H0[c*3 + j]));   // H0: (C,1,3)
        sh3[j] = softplus_acc(__ldg(&H3[c*3 + j]));   // H3: (C,3,1)
        ta0[j] = tanhf(__ldg(&a0[c*3 + j]));
        ta1[j] = tanhf(__ldg(&a1[c*3 + j]));
        ta2[j] = tanhf(__ldg(&a2[c*3 + j]));
        bb0[j] = __ldg(&b0[c*3 + j]);
        bb1[j] = __ldg(&b1[c*3 + j]);
        bb2[j] = __ldg(&b2[c*3 + j]);
    }
#pragma unroll
    for (int j = 0; j < 9; j++) {
        sh1[j] = softplus_acc(__ldg(&H1[c*9 + j]));   // H1: (C,3,3) [i*3+p]
        sh2[j] = softplus_acc(__ldg(&H2[c*9 + j]));
    }
    bb3 = __ldg(&b3[c]);

    for (int i = i0; i < n; i += stride) {
        float xv = x[i];
        float up = xv + 0.5f;
        float um = xv - 0.5f;

        // Layer 0: 1 -> 3
        float yp[3], ym[3];
#pragma unroll
        for (int j = 0; j < 3; j++) {
            float tp = fmaf(up, sh0[j], bb0[j]);
            float tm = fmaf(um, sh0[j], bb0[j]);
            yp[j] = fmaf(ta0[j], fast_tanh(tp), tp);
            ym[j] = fmaf(ta0[j], fast_tanh(tm), tm);
        }

        // Layer 1: 3 -> 3
        float zp[3], zm[3];
#pragma unroll
        for (int p = 0; p < 3; p++) {
            float sp = bb1[p], sm = bb1[p];
#pragma unroll
            for (int j = 0; j < 3; j++) {
                sp = fmaf(yp[j], sh1[j*3 + p], sp);
                sm = fmaf(ym[j], sh1[j*3 + p], sm);
            }
            zp[p] = fmaf(ta1[p], fast_tanh(sp), sp);
            zm[p] = fmaf(ta1[p], fast_tanh(sm), sm);
        }

        // Layer 2: 3 -> 3
#pragma unroll
        for (int p = 0; p < 3; p++) {
            float sp = bb2[p], sm = bb2[p];
#pragma unroll
            for (int j = 0; j < 3; j++) {
                sp = fmaf(zp[j], sh2[j*3 + p], sp);
                sm = fmaf(zm[j], sh2[j*3 + p], sm);
            }
            yp[p] = fmaf(ta2[p], fast_tanh(sp), sp);
            ym[p] = fmaf(ta2[p], fast_tanh(sm), sm);
        }

        // Layer 3: 3 -> 1, then difference of sigmoids
        float fp = bb3, fm = bb3;
#pragma unroll
        for (int j = 0; j < 3; j++) {
            fp = fmaf(yp[j], sh3[j], fp);
            fm = fmaf(ym[j], sh3[j], fm);
        }
        out[i] = fast_sigmoid(fp) - fast_sigmoid(fm);
    }
}

extern "C" void kernel_launch(void* const* d_in, const int* in_sizes, int n_in,
                              void* d_out, int out_size)
{
    const float* x  = (const float*)d_in[0];
    const float* a0 = (const float*)d_in[1];
    const float* a1 = (const float*)d_in[2];
    const float* a2 = (const float*)d_in[3];
    const float* b0 = (const float*)d_in[4];
    const float* b1 = (const float*)d_in[5];
    const float* b2 = (const float*)d_in[6];
    const float* b3 = (const float*)d_in[7];
    const float* H0 = (const float*)d_in[8];
    const float* H1 = (const float*)d_in[9];
    const float* H2 = (const float*)d_in[10];
    const float* H3 = (const float*)d_in[11];
    float* out = (float*)d_out;
    int n = in_sizes[0];   // 65536 * 192

    de_kernel<<<NBLK, NTHR>>>(x, a0, a1, a2, b0, b1, b2, b3,
                              H0, H1, H2, H3, out, n);
}

// round 2
// speedup vs baseline: 1.7940x; 1.7940x over previous
#include <cuda_runtime.h>
#include <cuda_bf16.h>

// DensityEstimator: per-channel 1->3->3->3->1 MLP, p = cdf(x+.5) - cdf(x-.5)
// R2: MUFU.TANH for inner activations (1 MUFU + 1 FMA each, vs 2 MUFU + 5 ALU),
// exact fused difference-of-sigmoids epilogue (2 ex2 + 1 shared rcp).
// Weights (softplus(H), tanh(a), biases) are batch-invariant -> registers,
// grid stride is a multiple of 192 so each thread's channel is fixed.

#define NCH 192
#define NBLK 888          // 888*256 = 227328 = 192*1184 -> channel invariant
#define NTHR 256

__device__ __forceinline__ float ex2a(float x) {
    float r; asm("ex2.approx.ftz.f32 %0, %1;" : "=f"(r) : "f"(x)); return r;
}
__device__ __forceinline__ float rcpa(float x) {
    float r; asm("rcp.approx.ftz.f32 %0, %1;" : "=f"(r) : "f"(x)); return r;
}
__device__ __forceinline__ float tanha(float x) {
    float r; asm("tanh.approx.f32 %0, %1;" : "=f"(r) : "f"(x)); return r;
}

// Accurate softplus for the one-time weight transform.
__device__ __forceinline__ float softplus_acc(float h) {
    return (h > 15.0f) ? h : log1pf(expf(h));
}

__global__ void __launch_bounds__(NTHR) de_kernel(
    const float* __restrict__ x,
    const float* __restrict__ a0, const float* __restrict__ a1, const float* __restrict__ a2,
    const float* __restrict__ b0, const float* __restrict__ b1, const float* __restrict__ b2,
    const float* __restrict__ b3,
    const float* __restrict__ H0, const float* __restrict__ H1, const float* __restrict__ H2,
    const float* __restrict__ H3,
    float* __restrict__ out, int n)
{
    const int stride = gridDim.x * blockDim.x;      // multiple of 192
    const int i0 = blockIdx.x * blockDim.x + threadIdx.x;
    const int c  = i0 % NCH;                        // fixed channel for this thread

    // One-time per-thread weight transform into registers.
    float sh0[3], sh1[9], sh2[9], sh3[3];
    float ta0[3], ta1[3], ta2[3];
    float bp0[3], bm0[3], bb1[3], bb2[3], bb3;
#pragma unroll
    for (int j = 0; j < 3; j++) {
        sh0[j] = softplus_acc(__ldg(&H0[c*3 + j]));   // H0: (C,1,3)
        sh3[j] = softplus_acc(__ldg(&H3[c*3 + j]));   // H3: (C,3,1)
        ta0[j] = tanhf(__ldg(&a0[c*3 + j]));
        ta1[j] = tanhf(__ldg(&a1[c*3 + j]));
        ta2[j] = tanhf(__ldg(&a2[c*3 + j]));
        float b0j = __ldg(&b0[c*3 + j]);
        bp0[j] = fmaf( 0.5f, sh0[j], b0j);            // fold x+0.5 into bias
        bm0[j] = fmaf(-0.5f, sh0[j], b0j);            // fold x-0.5 into bias
        bb1[j] = __ldg(&b1[c*3 + j]);
        bb2[j] = __ldg(&b2[c*3 + j]);
    }
#pragma unroll
    for (int j = 0; j < 9; j++) {
        sh1[j] = softplus_acc(__ldg(&H1[c*9 + j]));   // H1: (C,3,3) [i*3+p]
        sh2[j] = softplus_acc(__ldg(&H2[c*9 + j]));
    }
    bb3 = __ldg(&b3[c]);

    for (int i = i0; i < n; i += stride) {
        float xv = x[i];

        // Layer 0: 1 -> 3 (shifted biases absorb the +-0.5)
        float yp[3], ym[3];
#pragma unroll
        for (int j = 0; j < 3; j++) {
            float tp = fmaf(xv, sh0[j], bp0[j]);
            float tm = fmaf(xv, sh0[j], bm0[j]);
            yp[j] = fmaf(ta0[j], tanha(tp), tp);
            ym[j] = fmaf(ta0[j], tanha(tm), tm);
        }

        // Layer 1: 3 -> 3
        float zp[3], zm[3];
#pragma unroll
        for (int p = 0; p < 3; p++) {
            float sp = bb1[p], sm = bb1[p];
#pragma unroll
            for (int j = 0; j < 3; j++) {
                sp = fmaf(yp[j], sh1[j*3 + p], sp);
                sm = fmaf(ym[j], sh1[j*3 + p], sm);
            }
            zp[p] = fmaf(ta1[p], tanha(sp), sp);
            zm[p] = fmaf(ta1[p], tanha(sm), sm);
        }

        // Layer 2: 3 -> 3
#pragma unroll
        for (int p = 0; p < 3; p++) {
            float sp = bb2[p], sm = bb2[p];
#pragma unroll
            for (int j = 0; j < 3; j++) {
                sp = fmaf(zp[j], sh2[j*3 + p], sp);
                sm = fmaf(zm[j], sh2[j*3 + p], sm);
            }
            yp[p] = fmaf(ta2[p], tanha(sp), sp);
            ym[p] = fmaf(ta2[p], tanha(sm), sm);
        }

        // Layer 3: 3 -> 1
        float fp = bb3, fm = bb3;
#pragma unroll
        for (int j = 0; j < 3; j++) {
            fp = fmaf(yp[j], sh3[j], fp);
            fm = fmaf(ym[j], sh3[j], fm);
        }

        // Exact fused difference of sigmoids:
        // sigma(fp) - sigma(fm) = (e^-fm - e^-fp) / ((1+e^-fp)(1+e^-fm))
        // Clamp to +-30 so the denominator product stays finite (<= ~1.1e26).
        float fpc = fminf(fmaxf(fp, -30.0f), 30.0f);
        float fmc = fminf(fmaxf(fm, -30.0f), 30.0f);
        float ep = ex2a(-1.4426950408889634f * fpc);   // e^-fp
        float em = ex2a(-1.4426950408889634f * fmc);   // e^-fm
        float r  = rcpa((1.0f + ep) * (1.0f + em));
        out[i] = (em - ep) * r;
    }
}

extern "C" void kernel_launch(void* const* d_in, const int* in_sizes, int n_in,
                              void* d_out, int out_size)
{
    const float* x  = (const float*)d_in[0];
    const float* a0 = (const float*)d_in[1];
    const float* a1 = (const float*)d_in[2];
    const float* a2 = (const float*)d_in[3];
    const float* b0 = (const float*)d_in[4];
    const float* b1 = (const float*)d_in[5];
    const float* b2 = (const float*)d_in[6];
    const float* b3 = (const float*)d_in[7];
    const float* H0 = (const float*)d_in[8];
    const float* H1 = (const float*)d_in[9];
    const float* H2 = (const float*)d_in[10];
    const float* H3 = (const float*)d_in[11];
    float* out = (float*)d_out;
    int n = in_sizes[0];   // 65536 * 192

    de_kernel<<<NBLK, NTHR>>>(x, a0, a1, a2, b0, b1, b2, b3,
                              H0, H1, H2, H3, out, n);
}